// round 2
// baseline (speedup 1.0000x reference)
#include <cuda_runtime.h>

// Push-DIGing on GB300. N=20000 nodes, D=64 features, E=320000 edges, 10 layers.
//  - edge_index is int32 (JAX x64 disabled downcasts int64 -> int32)
//  - g0 cached from previous layer's g1 -> 10 grad passes instead of 21
//  - final layer skips y-update (doesn't affect output x1)
//  - vectorized red.global.add.v4.f32 for segment-sum scatter
//  - warp-per-row coalesced batched matvec for grad

#define NN 20000
#define DD 64
#define EE 320000
#define NL 10
#define STEP 0.01f
#define ND (NN * DD)

// Scratch (allocation-free rule: __device__ globals)
__device__ float g_uA[ND], g_uB[ND];
__device__ float g_yA[ND], g_yB[ND];
__device__ float g_gA[ND], g_gB[ND];
__device__ float g_x1[ND];
__device__ float g_vA[NN], g_vB[NN];
__device__ float g_invd[NN];
__device__ int   g_cnt[NN];

__device__ __forceinline__ void red4(float* a, float x, float y, float z, float w) {
    asm volatile("red.global.add.v4.f32 [%0], {%1,%2,%3,%4};"
                 :: "l"(a), "f"(x), "f"(y), "f"(z), "f"(w) : "memory");
}

__global__ void k_cnt0() {
    int n = blockIdx.x * blockDim.x + threadIdx.x;
    if (n < NN) g_cnt[n] = 0;
}

__global__ void k_count(const int* __restrict__ ei) {
    int e = blockIdx.x * blockDim.x + threadIdx.x;
    if (e < EE) atomicAdd(&g_cnt[ei[e]], 1);
}

__global__ void k_invd() {
    int n = blockIdx.x * blockDim.x + threadIdx.x;
    if (n < NN) {
        g_invd[n] = 1.0f / (1.0f + (float)g_cnt[n]);
        g_vA[n] = 1.0f;
    }
}

// g = 2*A@x + b  (warp per row; lane loads float2 of A row -> coalesced 256B)
__global__ void __launch_bounds__(256) k_grad(const float* __restrict__ A,
                                              const float* __restrict__ b,
                                              const float* __restrict__ x,
                                              float* __restrict__ g) {
    int w = (blockIdx.x * blockDim.x + threadIdx.x) >> 5;
    int lane = threadIdx.x & 31;
    if (w >= ND) return;
    int node = w >> 6;
    float2 a2 = __ldg((const float2*)(A + (size_t)w * DD) + lane);
    float2 x2 = __ldg((const float2*)(x + node * DD) + lane);
    float p = a2.x * x2.x + a2.y * x2.y;
#pragma unroll
    for (int o = 16; o; o >>= 1) p += __shfl_xor_sync(0xffffffffu, p, o);
    if (lane == 0) g[w] = 2.0f * p + __ldg(b + w);
}

// Self-loop init of aggregation buffers: agg = z * inv_deg (z = u - h*y for u-path)
__global__ void __launch_bounds__(256) k_init(const float* __restrict__ u,
                                              const float* __restrict__ y,
                                              const float* __restrict__ v,
                                              float* __restrict__ au,
                                              float* __restrict__ ay,
                                              float* __restrict__ av,
                                              int doY) {
    int gid = blockIdx.x * blockDim.x + threadIdx.x;
    if (gid >= NN * 16) return;
    int n = gid >> 4, q = gid & 15;
    float w = g_invd[n];
    int base = n * DD + q * 4;
    float4 u4 = *(const float4*)(u + base);
    float4 y4 = *(const float4*)(y + base);
    float4 r;
    r.x = (u4.x - STEP * y4.x) * w;
    r.y = (u4.y - STEP * y4.y) * w;
    r.z = (u4.z - STEP * y4.z) * w;
    r.w = (u4.w - STEP * y4.w) * w;
    *(float4*)(au + base) = r;
    if (doY) {
        float4 t;
        t.x = y4.x * w; t.y = y4.y * w; t.z = y4.z * w; t.w = y4.w * w;
        *(float4*)(ay + base) = t;
    }
    if (q == 0) av[n] = v[n] * w;
}

// Edge scatter: agg[dst] += z[src] * inv_deg[src]  (vectorized red.add)
__global__ void __launch_bounds__(256) k_scatter(const int* __restrict__ ei,
                                                 const float* __restrict__ u,
                                                 const float* __restrict__ y,
                                                 const float* __restrict__ v,
                                                 float* __restrict__ au,
                                                 float* __restrict__ ay,
                                                 float* __restrict__ av,
                                                 int doY) {
    int gid = blockIdx.x * blockDim.x + threadIdx.x;
    if (gid >= EE * 16) return;
    int e = gid >> 4, q = gid & 15;
    int s = __ldg(ei + e);
    int d = __ldg(ei + EE + e);
    float w = g_invd[s];
    int sb = s * DD + q * 4;
    int db = d * DD + q * 4;
    float4 u4 = __ldg((const float4*)(u + sb));
    float4 y4 = __ldg((const float4*)(y + sb));
    red4(au + db,
         (u4.x - STEP * y4.x) * w,
         (u4.y - STEP * y4.y) * w,
         (u4.z - STEP * y4.z) * w,
         (u4.w - STEP * y4.w) * w);
    if (doY) red4(ay + db, y4.x * w, y4.y * w, y4.z * w, y4.w * w);
    if (q == 0) atomicAdd(av + d, __ldg(v + s) * w);
}

// x1 = u_new / v_new
__global__ void __launch_bounds__(256) k_x1(const float* __restrict__ au,
                                            const float* __restrict__ av,
                                            float* __restrict__ o) {
    int gid = blockIdx.x * blockDim.x + threadIdx.x;
    if (gid >= NN * 16) return;
    int n = gid >> 4, q = gid & 15;
    float inv = 1.0f / av[n];
    int base = n * DD + q * 4;
    float4 u4 = *(const float4*)(au + base);
    float4 r;
    r.x = u4.x * inv; r.y = u4.y * inv; r.z = u4.z * inv; r.w = u4.w * inv;
    *(float4*)(o + base) = r;
}

// y_new = mix(y) + g1 - g0 (ay already holds mix(y))
__global__ void __launch_bounds__(256) k_yfix(float* __restrict__ ay,
                                              const float* __restrict__ g1,
                                              const float* __restrict__ g0) {
    int gid = blockIdx.x * blockDim.x + threadIdx.x;
    if (gid >= ND / 4) return;
    float4 a = ((float4*)ay)[gid];
    float4 p = ((const float4*)g1)[gid];
    float4 m = ((const float4*)g0)[gid];
    a.x += p.x - m.x; a.y += p.y - m.y; a.z += p.z - m.z; a.w += p.w - m.w;
    ((float4*)ay)[gid] = a;
}

__global__ void k_tail(float* o, int start, int end, float val) {
    int i = start + blockIdx.x * blockDim.x + threadIdx.x;
    if (i < end) o[i] = val;
}

extern "C" void kernel_launch(void* const* d_in, const int* in_sizes, int n_in,
                              void* d_out, int out_size) {
    const float* A = (const float*)d_in[0];
    const float* b = (const float*)d_in[1];
    const float* x = (const float*)d_in[2];
    const int* ei = (const int*)d_in[3];   // int32: JAX default x64-disabled
    float* out = (float*)d_out;

    float *uA, *uB, *yA, *yB, *gA, *gB, *x1, *vA, *vB;
    cudaGetSymbolAddress((void**)&uA, g_uA);
    cudaGetSymbolAddress((void**)&uB, g_uB);
    cudaGetSymbolAddress((void**)&yA, g_yA);
    cudaGetSymbolAddress((void**)&yB, g_yB);
    cudaGetSymbolAddress((void**)&gA, g_gA);
    cudaGetSymbolAddress((void**)&gB, g_gB);
    cudaGetSymbolAddress((void**)&x1, g_x1);
    cudaGetSymbolAddress((void**)&vA, g_vA);
    cudaGetSymbolAddress((void**)&vB, g_vB);

    // degree -> inv_deg, v = ones
    k_cnt0<<<(NN + 255) / 256, 256>>>();
    k_count<<<(EE + 255) / 256, 256>>>(ei);
    k_invd<<<(NN + 255) / 256, 256>>>();

    // initial y = grad(x); this also serves as g0 for layer 0
    k_grad<<<ND / 8, 256>>>(A, b, x, gA);

    const float* u_in = x;
    const float* y_in = gA;
    const float* v_in = vA;
    const float* g_in = gA;

    for (int L = 0; L < NL; L++) {
        int doY = (L < NL - 1);
        float* u_out = (L & 1) ? uB : uA;
        float* y_out = (L & 1) ? yB : yA;
        float* v_out = (L & 1) ? vA : vB;
        float* g_out = (L & 1) ? gA : gB;
        float* xo = (L == NL - 1) ? out : x1;

        k_init<<<(NN * 16) / 256, 256>>>(u_in, y_in, v_in, u_out, y_out, v_out, doY);
        k_scatter<<<(EE * 16) / 256, 256>>>(ei, u_in, y_in, v_in, u_out, y_out, v_out, doY);
        k_x1<<<(NN * 16) / 256, 256>>>(u_out, v_out, xo);
        if (doY) {
            k_grad<<<ND / 8, 256>>>(A, b, xo, g_out);
            k_yfix<<<(ND / 4) / 256, 256>>>(y_out, g_out, g_in);
        }
        u_in = u_out; y_in = y_out; v_in = v_out; g_in = g_out;
    }

    // comm_cost tail (only if the harness folded it into this buffer)
    if (out_size > ND) {
        float cc = (float)(3LL * NL * (long long)EE);
        int tail = out_size - ND;
        k_tail<<<(tail + 255) / 256, 256>>>(out, ND, out_size, cc);
    }
}

// round 3
// speedup vs baseline: 1.8661x; 1.8661x over previous
#include <cuda_runtime.h>

// Push-DIGing on GB300. N=20000, D=64, E=320000, 10 layers.
// R3: warp-per-node gradient (LDG.128, 2 rows/load, 4-shfl reduce, unroll-8 ILP),
//     x1 and y-fix fused into the gradient kernel.

#define NN 20000
#define DD 64
#define EE 320000
#define NL 10
#define STEP 0.01f
#define ND (NN * DD)

__device__ float g_uA[ND], g_uB[ND];
__device__ float g_yA[ND], g_yB[ND];
__device__ float g_gA[ND], g_gB[ND];
__device__ float g_vA[NN], g_vB[NN];
__device__ float g_invd[NN];
__device__ int   g_cnt[NN];

__device__ __forceinline__ void red4(float* a, float x, float y, float z, float w) {
    asm volatile("red.global.add.v4.f32 [%0], {%1,%2,%3,%4};"
                 :: "l"(a), "f"(x), "f"(y), "f"(z), "f"(w) : "memory");
}

__global__ void k_cnt0() {
    int n = blockIdx.x * blockDim.x + threadIdx.x;
    if (n < NN) g_cnt[n] = 0;
}

__global__ void k_count(const int* __restrict__ ei) {
    int e = blockIdx.x * blockDim.x + threadIdx.x;
    if (e < EE) atomicAdd(&g_cnt[ei[e]], 1);
}

__global__ void k_invd() {
    int n = blockIdx.x * blockDim.x + threadIdx.x;
    if (n < NN) {
        g_invd[n] = 1.0f / (1.0f + (float)g_cnt[n]);
        g_vA[n] = 1.0f;
    }
}

// Fused gradient: x = u * (av ? 1/av[n] : 1);  g = 2*A@x + b;
// optional: ay[r] += g[r] - g0[r]  (y-update fused)
// One warp per node. Each LDG.128 covers 2 rows (512B contiguous).
__global__ void __launch_bounds__(256) k_gradx(const float* __restrict__ A,
                                               const float* __restrict__ b,
                                               const float* __restrict__ u,
                                               const float* __restrict__ av,
                                               float* __restrict__ g,
                                               float* __restrict__ ay,
                                               const float* __restrict__ g0) {
    int w = (blockIdx.x * blockDim.x + threadIdx.x) >> 5;
    if (w >= NN) return;
    int lane = threadIdx.x & 31;
    int hl = lane >> 4;        // 0: row 2i, 1: row 2i+1
    int sl = lane & 15;        // position within row (float4 granules)

    float inv = av ? (1.0f / __ldg(av + w)) : 1.0f;
    float4 x4 = __ldg((const float4*)(u + w * DD) + sl);
    x4.x *= inv; x4.y *= inv; x4.z *= inv; x4.w *= inv;

    const float4* Ab = (const float4*)(A + (size_t)w * DD * DD);
#pragma unroll 8
    for (int i = 0; i < 32; i++) {
        float4 a4 = __ldg(Ab + i * 32 + lane);
        float p = a4.x * x4.x + a4.y * x4.y + a4.z * x4.z + a4.w * x4.w;
        p += __shfl_xor_sync(0xffffffffu, p, 1);
        p += __shfl_xor_sync(0xffffffffu, p, 2);
        p += __shfl_xor_sync(0xffffffffu, p, 4);
        p += __shfl_xor_sync(0xffffffffu, p, 8);
        if (sl == 0) {
            int r = w * DD + 2 * i + hl;
            float gv = 2.0f * p + __ldg(b + r);
            g[r] = gv;
            if (ay) ay[r] += gv - __ldg(g0 + r);
        }
    }
}

// Self-loop init: au = (u - h*y)*w ; ay = y*w ; av = v*w
__global__ void __launch_bounds__(256) k_init(const float* __restrict__ u,
                                              const float* __restrict__ y,
                                              const float* __restrict__ v,
                                              float* __restrict__ au,
                                              float* __restrict__ ay,
                                              float* __restrict__ av,
                                              int doY) {
    int gid = blockIdx.x * blockDim.x + threadIdx.x;
    if (gid >= NN * 16) return;
    int n = gid >> 4, q = gid & 15;
    float w = g_invd[n];
    int base = n * DD + q * 4;
    float4 u4 = *(const float4*)(u + base);
    float4 y4 = *(const float4*)(y + base);
    float4 r;
    r.x = (u4.x - STEP * y4.x) * w;
    r.y = (u4.y - STEP * y4.y) * w;
    r.z = (u4.z - STEP * y4.z) * w;
    r.w = (u4.w - STEP * y4.w) * w;
    *(float4*)(au + base) = r;
    if (doY) {
        float4 t;
        t.x = y4.x * w; t.y = y4.y * w; t.z = y4.z * w; t.w = y4.w * w;
        *(float4*)(ay + base) = t;
    }
    if (q == 0) av[n] = v[n] * w;
}

// Edge scatter: agg[dst] += z[src]*inv_deg[src]
__global__ void __launch_bounds__(256) k_scatter(const int* __restrict__ ei,
                                                 const float* __restrict__ u,
                                                 const float* __restrict__ y,
                                                 const float* __restrict__ v,
                                                 float* __restrict__ au,
                                                 float* __restrict__ ay,
                                                 float* __restrict__ av,
                                                 int doY) {
    int gid = blockIdx.x * blockDim.x + threadIdx.x;
    if (gid >= EE * 16) return;
    int e = gid >> 4, q = gid & 15;
    int s = __ldg(ei + e);
    int d = __ldg(ei + EE + e);
    float w = g_invd[s];
    int sb = s * DD + q * 4;
    int db = d * DD + q * 4;
    float4 u4 = __ldg((const float4*)(u + sb));
    float4 y4 = __ldg((const float4*)(y + sb));
    red4(au + db,
         (u4.x - STEP * y4.x) * w,
         (u4.y - STEP * y4.y) * w,
         (u4.z - STEP * y4.z) * w,
         (u4.w - STEP * y4.w) * w);
    if (doY) red4(ay + db, y4.x * w, y4.y * w, y4.z * w, y4.w * w);
    if (q == 0) atomicAdd(av + d, __ldg(v + s) * w);
}

// Final-layer x1 = u_new / v_new -> out
__global__ void __launch_bounds__(256) k_x1(const float* __restrict__ au,
                                            const float* __restrict__ av,
                                            float* __restrict__ o) {
    int gid = blockIdx.x * blockDim.x + threadIdx.x;
    if (gid >= NN * 16) return;
    int n = gid >> 4, q = gid & 15;
    float inv = 1.0f / av[n];
    int base = n * DD + q * 4;
    float4 u4 = *(const float4*)(au + base);
    float4 r;
    r.x = u4.x * inv; r.y = u4.y * inv; r.z = u4.z * inv; r.w = u4.w * inv;
    *(float4*)(o + base) = r;
}

__global__ void k_tail(float* o, int start, int end, float val) {
    int i = start + blockIdx.x * blockDim.x + threadIdx.x;
    if (i < end) o[i] = val;
}

extern "C" void kernel_launch(void* const* d_in, const int* in_sizes, int n_in,
                              void* d_out, int out_size) {
    const float* A = (const float*)d_in[0];
    const float* b = (const float*)d_in[1];
    const float* x = (const float*)d_in[2];
    const int* ei = (const int*)d_in[3];   // int32 (JAX x64 disabled)
    float* out = (float*)d_out;

    float *uA, *uB, *yA, *yB, *gA, *gB, *vA, *vB;
    cudaGetSymbolAddress((void**)&uA, g_uA);
    cudaGetSymbolAddress((void**)&uB, g_uB);
    cudaGetSymbolAddress((void**)&yA, g_yA);
    cudaGetSymbolAddress((void**)&yB, g_yB);
    cudaGetSymbolAddress((void**)&gA, g_gA);
    cudaGetSymbolAddress((void**)&gB, g_gB);
    cudaGetSymbolAddress((void**)&vA, g_vA);
    cudaGetSymbolAddress((void**)&vB, g_vB);

    k_cnt0<<<(NN + 255) / 256, 256>>>();
    k_count<<<(EE + 255) / 256, 256>>>(ei);
    k_invd<<<(NN + 255) / 256, 256>>>();

    // initial y = grad(x); also serves as g0 for layer 0
    k_gradx<<<(NN * 32 + 255) / 256, 256>>>(A, b, x, nullptr, gA, nullptr, nullptr);

    const float* u_in = x;
    const float* y_in = gA;
    const float* v_in = vA;
    const float* g_in = gA;

    for (int L = 0; L < NL; L++) {
        int doY = (L < NL - 1);
        float* u_out = (L & 1) ? uB : uA;
        float* y_out = (L & 1) ? yB : yA;
        float* v_out = (L & 1) ? vA : vB;
        float* g_out = (L & 1) ? gA : gB;

        k_init<<<(NN * 16) / 256, 256>>>(u_in, y_in, v_in, u_out, y_out, v_out, doY);
        k_scatter<<<(EE * 16) / 256, 256>>>(ei, u_in, y_in, v_in, u_out, y_out, v_out, doY);
        if (doY) {
            // fused: x1 = au/av, g1 = grad(x1), y_out += g1 - g0
            k_gradx<<<(NN * 32 + 255) / 256, 256>>>(A, b, u_out, v_out, g_out, y_out, g_in);
        } else {
            k_x1<<<(NN * 16) / 256, 256>>>(u_out, v_out, out);
        }
        u_in = u_out; y_in = y_out; v_in = v_out; g_in = g_out;
    }

    if (out_size > ND) {
        float cc = (float)(3LL * NL * (long long)EE);
        int tail = out_size - ND;
        k_tail<<<(tail + 255) / 256, 256>>>(out, ND, out_size, cc);
    }
}

// round 4
// speedup vs baseline: 1.9312x; 1.0349x over previous
#include <cuda_runtime.h>

// Push-DIGing on GB300. N=20000, D=64, E=320000, 10 layers.
// R4: smem-staged shuffle-free grad (node-per-block, XOR-swizzled),
//     next-layer self-loop init fused into grad epilogue,
//     edges counting-sorted by src for gather L1 locality.

#define NN 20000
#define DD 64
#define EE 320000
#define NL 10
#define STEP 0.01f
#define ND (NN * DD)

__device__ float g_auA[ND], g_auB[ND];
__device__ float g_ayA[ND], g_ayB[ND];
__device__ float g_gA[ND],  g_gB[ND];
__device__ float g_avA[NN], g_avB[NN];
__device__ float g_invd[NN];
__device__ int   g_cnt[NN];
__device__ int   g_pos[NN];
__device__ int   g_es[EE], g_ed[EE];

__device__ __forceinline__ void red4(float* a, float x, float y, float z, float w) {
    asm volatile("red.global.add.v4.f32 [%0], {%1,%2,%3,%4};"
                 :: "l"(a), "f"(x), "f"(y), "f"(z), "f"(w) : "memory");
}

__global__ void k_cnt0() {
    int n = blockIdx.x * blockDim.x + threadIdx.x;
    if (n < NN) g_cnt[n] = 0;
}

__global__ void k_count(const int* __restrict__ ei) {
    int e = blockIdx.x * blockDim.x + threadIdx.x;
    if (e < EE) atomicAdd(&g_cnt[ei[e]], 1);
}

__global__ void k_invd() {
    int n = blockIdx.x * blockDim.x + threadIdx.x;
    if (n < NN) g_invd[n] = 1.0f / (1.0f + (float)g_cnt[n]);
}

// Exclusive prefix sum of g_cnt -> g_pos (single block, 1024 threads x 20)
__global__ void __launch_bounds__(1024) k_scan() {
    __shared__ int sp[1024];
    int t = threadIdx.x;
    int base = t * 20;
    int loc[20];
    int s = 0;
#pragma unroll
    for (int i = 0; i < 20; i++) {
        int idx = base + i;
        int c = (idx < NN) ? g_cnt[idx] : 0;
        loc[i] = s;
        s += c;
    }
    sp[t] = s;
    __syncthreads();
    for (int o = 1; o < 1024; o <<= 1) {
        int v = (t >= o) ? sp[t - o] : 0;
        __syncthreads();
        sp[t] += v;
        __syncthreads();
    }
    int pre = (t == 0) ? 0 : sp[t - 1];
#pragma unroll
    for (int i = 0; i < 20; i++) {
        int idx = base + i;
        if (idx < NN) g_pos[idx] = pre + loc[i];
    }
}

// Counting-sort placement: edges grouped by src
__global__ void k_sort(const int* __restrict__ ei) {
    int e = blockIdx.x * blockDim.x + threadIdx.x;
    if (e >= EE) return;
    int s = ei[e];
    int d = ei[e + EE];
    int p = atomicAdd(&g_pos[s], 1);
    g_es[p] = s;
    g_ed[p] = d;
}

// Fused grad: x = u/vnew; g1 = 2*A@x + b; ynew = ay + g1 - g0 (or ynew=g1 first call);
// writes next-layer self-loop inits: auN=(u-h*ynew)*w, ayN=ynew*w, avN=vnew*w.
// One node per 64-thread block; A staged in smem with XOR swizzle, no shuffles.
__global__ void __launch_bounds__(64) k_gradx(const float* __restrict__ A,
                                              const float* __restrict__ b,
                                              const float* __restrict__ u,
                                              const float* __restrict__ av,
                                              float* __restrict__ g,
                                              float* __restrict__ ay,
                                              const float* __restrict__ g0,
                                              float* __restrict__ auN,
                                              float* __restrict__ ayN,
                                              float* __restrict__ avN) {
    __shared__ float sA[DD * DD];   // 16KB, float4-col swizzled: cs = c ^ (r&15)
    __shared__ float sx[DD];
    int n = blockIdx.x;
    int t = threadIdx.x;

    float vnew = av ? __ldg(av + n) : 1.0f;
    float inv = 1.0f / vnew;

    if (t < 16) {
        float4 u4 = __ldg((const float4*)(u + n * DD) + t);
        u4.x *= inv; u4.y *= inv; u4.z *= inv; u4.w *= inv;
        ((float4*)sx)[t] = u4;
    }

    const float4* Ab = (const float4*)(A + (size_t)n * DD * DD);
#pragma unroll
    for (int k = 0; k < 16; k++) {
        float4 a4 = __ldg(Ab + k * 64 + t);
        int r = k * 4 + (t >> 4);
        int c = t & 15;
        ((float4*)sA)[r * 16 + (c ^ (r & 15))] = a4;
    }
    __syncthreads();

    float acc = 0.0f;
#pragma unroll
    for (int j = 0; j < 16; j++) {
        float4 a4 = ((const float4*)sA)[t * 16 + (j ^ (t & 15))];
        float4 x4 = ((const float4*)sx)[j];
        acc += a4.x * x4.x + a4.y * x4.y + a4.z * x4.z + a4.w * x4.w;
    }

    int r = n * DD + t;
    float w = g_invd[n];
    float gv = 2.0f * acc + __ldg(b + r);
    g[r] = gv;
    float ynew;
    if (ay) {
        ynew = ay[r] + gv - __ldg(g0 + r);
        ay[r] = ynew;
    } else {
        ynew = gv;   // first call: y0 = grad(x0)
    }
    float uval = sx[t] * vnew;
    auN[r] = (uval - STEP * ynew) * w;
    ayN[r] = ynew * w;
    if (t == 0) avN[n] = vnew * w;
}

// Edge scatter over src-sorted edges: agg[dst] += z[src]*w[src]
__global__ void __launch_bounds__(256) k_scatter(const float* __restrict__ u,
                                                 const float* __restrict__ y,
                                                 const float* __restrict__ v,
                                                 float* __restrict__ au,
                                                 float* __restrict__ ay,
                                                 float* __restrict__ av,
                                                 int doY) {
    int gid = blockIdx.x * blockDim.x + threadIdx.x;
    if (gid >= EE * 16) return;
    int e = gid >> 4, q = gid & 15;
    int s = g_es[e];
    int d = g_ed[e];
    float w = g_invd[s];
    int sb = s * DD + q * 4;
    int db = d * DD + q * 4;
    float4 u4 = __ldg((const float4*)(u + sb));
    float4 y4 = __ldg((const float4*)(y + sb));
    red4(au + db,
         (u4.x - STEP * y4.x) * w,
         (u4.y - STEP * y4.y) * w,
         (u4.z - STEP * y4.z) * w,
         (u4.w - STEP * y4.w) * w);
    if (doY) red4(ay + db, y4.x * w, y4.y * w, y4.z * w, y4.w * w);
    if (q == 0) atomicAdd(av + d, (v ? __ldg(v + s) : 1.0f) * w);
}

// First-layer scatter reads v implicitly = 1 (v==nullptr path above)

// Final x1 = u_new / v_new -> out
__global__ void __launch_bounds__(256) k_x1(const float* __restrict__ au,
                                            const float* __restrict__ av,
                                            float* __restrict__ o) {
    int gid = blockIdx.x * blockDim.x + threadIdx.x;
    if (gid >= NN * 16) return;
    int n = gid >> 4, q = gid & 15;
    float inv = 1.0f / av[n];
    int base = n * DD + q * 4;
    float4 u4 = *(const float4*)(au + base);
    float4 r;
    r.x = u4.x * inv; r.y = u4.y * inv; r.z = u4.z * inv; r.w = u4.w * inv;
    *(float4*)(o + base) = r;
}

__global__ void k_tail(float* o, int start, int end, float val) {
    int i = start + blockIdx.x * blockDim.x + threadIdx.x;
    if (i < end) o[i] = val;
}

extern "C" void kernel_launch(void* const* d_in, const int* in_sizes, int n_in,
                              void* d_out, int out_size) {
    const float* A = (const float*)d_in[0];
    const float* b = (const float*)d_in[1];
    const float* x = (const float*)d_in[2];
    const int* ei = (const int*)d_in[3];   // int32 (JAX x64 disabled)
    float* out = (float*)d_out;

    float *auA, *auB, *ayA, *ayB, *gA, *gB, *avA, *avB;
    cudaGetSymbolAddress((void**)&auA, g_auA);
    cudaGetSymbolAddress((void**)&auB, g_auB);
    cudaGetSymbolAddress((void**)&ayA, g_ayA);
    cudaGetSymbolAddress((void**)&ayB, g_ayB);
    cudaGetSymbolAddress((void**)&gA, g_gA);
    cudaGetSymbolAddress((void**)&gB, g_gB);
    cudaGetSymbolAddress((void**)&avA, g_avA);
    cudaGetSymbolAddress((void**)&avB, g_avB);

    // setup: degrees, inv weights, sorted edge list
    k_cnt0<<<(NN + 255) / 256, 256>>>();
    k_count<<<(EE + 255) / 256, 256>>>(ei);
    k_invd<<<(NN + 255) / 256, 256>>>();
    k_scan<<<1, 1024>>>();
    k_sort<<<(EE + 255) / 256, 256>>>(ei);

    // gradx0: y0 = grad(x); set A gets self-loop inits for layer 0
    k_gradx<<<NN, 64>>>(A, b, x, nullptr, gA, nullptr, nullptr, auA, ayA, avA);

    // layer-0 message sources: u=x, y=gA (y0), v=ones (nullptr)
    const float *u_in = x, *y_in = gA, *v_in = nullptr;
    float* g_prev = gA;

    for (int L = 0; L < NL; L++) {
        int p = L & 1;                       // accumulate into set P this layer
        float* auP = p ? auB : auA;
        float* ayP = p ? ayB : ayA;
        float* avP = p ? avB : avA;
        float* auQ = p ? auA : auB;          // gradx writes next-layer inits
        float* ayQ = p ? ayA : ayB;
        float* avQ = p ? avA : avB;
        int doY = (L < NL - 1);

        k_scatter<<<(EE * 16) / 256, 256>>>(u_in, y_in, v_in, auP, ayP, avP, doY);
        // after scatter: auP=u_{L+1}, ayP=mix(y_L), avP=v_{L+1}

        if (doY) {
            float* g_cur = (p ? gB : gA) == g_prev ? (p ? gA : gB) : (p ? gB : gA);
            // simpler: alternate explicitly
            g_cur = (L & 1) ? gA : gB;
            k_gradx<<<NN, 64>>>(A, b, auP, avP, g_cur, ayP, g_prev, auQ, ayQ, avQ);
            // ayP now = y_{L+1}; set Q holds self-inits for layer L+1
            u_in = auP; y_in = ayP; v_in = avP;
            g_prev = g_cur;
        } else {
            k_x1<<<(NN * 16) / 256, 256>>>(auP, avP, out);
        }
    }

    if (out_size > ND) {
        float cc = (float)(3LL * NL * (long long)EE);
        int tail = out_size - ND;
        k_tail<<<(tail + 255) / 256, 256>>>(out, ND, out_size, cc);
    }
}

// round 5
// speedup vs baseline: 2.3937x; 1.2395x over previous
#include <cuda_runtime.h>
#include <cstdint>

// Push-DIGing on GB300. N=20000, D=64, E=320000, 10 layers.
// R5: pull-based fully fused layer kernel. Grad epilogue emits premultiplied
// messages mu=(u-h*y)*w, my=y*w, mv=v*w; next layer gathers over in-CSR,
// divides, matvecs with cp.async-staged A, updates y, emits next messages.
// No atomics in the loop; one kernel per layer.

#define NN 20000
#define DD 64
#define EE 320000
#define NL 10
#define STEP 0.01f
#define ND (NN * DD)

__device__ float g_muA[ND], g_muB[ND];
__device__ float g_myA[ND], g_myB[ND];
__device__ float g_mvA[NN], g_mvB[NN];
__device__ float g_g[ND];
__device__ float g_invd[NN];
__device__ int   g_cin[NN];    // in-degree (dst counts)
__device__ int   g_cout[NN];   // out-degree (src counts)
__device__ int   g_rs[NN + 1]; // CSR row starts by dst
__device__ int   g_pos[NN];    // scratch cursor for sort
__device__ int   g_src[EE];    // src ids grouped by dst

__global__ void k_cnt0() {
    int n = blockIdx.x * blockDim.x + threadIdx.x;
    if (n < NN) { g_cin[n] = 0; g_cout[n] = 0; }
}

__global__ void k_count(const int* __restrict__ ei) {
    int e = blockIdx.x * blockDim.x + threadIdx.x;
    if (e < EE) {
        atomicAdd(&g_cout[ei[e]], 1);
        atomicAdd(&g_cin[ei[e + EE]], 1);
    }
}

__global__ void k_invd() {
    int n = blockIdx.x * blockDim.x + threadIdx.x;
    if (n < NN) g_invd[n] = 1.0f / (1.0f + (float)g_cout[n]);
}

// Exclusive scan of in-degrees -> g_rs, g_pos (single block; int4 loads)
__global__ void __launch_bounds__(1024) k_scan() {
    __shared__ int sp[1024];
    int t = threadIdx.x;
    int base = t * 20;           // 20*1024 = 20480 >= NN
    int loc[20];
    int s = 0;
    int4 buf[5];
#pragma unroll
    for (int q = 0; q < 5; q++) {
        int idx = base + q * 4;
        if (idx + 3 < NN) buf[q] = *(const int4*)(g_cin + idx);
        else {
            buf[q].x = (idx + 0 < NN) ? g_cin[idx + 0] : 0;
            buf[q].y = (idx + 1 < NN) ? g_cin[idx + 1] : 0;
            buf[q].z = (idx + 2 < NN) ? g_cin[idx + 2] : 0;
            buf[q].w = (idx + 3 < NN) ? g_cin[idx + 3] : 0;
        }
    }
#pragma unroll
    for (int q = 0; q < 5; q++) {
        loc[q * 4 + 0] = s; s += buf[q].x;
        loc[q * 4 + 1] = s; s += buf[q].y;
        loc[q * 4 + 2] = s; s += buf[q].z;
        loc[q * 4 + 3] = s; s += buf[q].w;
    }
    sp[t] = s;
    __syncthreads();
    for (int o = 1; o < 1024; o <<= 1) {
        int v = (t >= o) ? sp[t - o] : 0;
        __syncthreads();
        sp[t] += v;
        __syncthreads();
    }
    int pre = (t == 0) ? 0 : sp[t - 1];
#pragma unroll
    for (int i = 0; i < 20; i++) {
        int idx = base + i;
        if (idx < NN) { g_rs[idx] = pre + loc[i]; g_pos[idx] = pre + loc[i]; }
    }
    if (t == 0) g_rs[NN] = EE;
}

// Group srcs by dst
__global__ void k_sort(const int* __restrict__ ei) {
    int e = blockIdx.x * blockDim.x + threadIdx.x;
    if (e >= EE) return;
    int s = ei[e];
    int d = ei[e + EE];
    int p = atomicAdd(&g_pos[d], 1);
    g_src[p] = s;
}

// Fused layer kernel (one 64-thread block per node):
//   first=1 : u=xin, y-mix skipped, v=1 -> y0 = g(x); emit messages
//   first=0 : gather mu/my/mv over in-CSR + self; x1=u/v; g1=2Ax1+b;
//             ynew = mix(y)+g1-g[r]; g[r]=g1; emit next messages
__global__ void __launch_bounds__(64) k_fused(const float* __restrict__ A,
                                              const float* __restrict__ b,
                                              const float* __restrict__ xin,
                                              const float* __restrict__ mu,
                                              const float* __restrict__ my,
                                              const float* __restrict__ mv,
                                              float* __restrict__ g,
                                              float* __restrict__ muN,
                                              float* __restrict__ myN,
                                              float* __restrict__ mvN,
                                              int first) {
    __shared__ float4 sA[DD * 16];   // 16KB, col-swizzled c^(r&15)
    __shared__ float sx[DD];
    int d = blockIdx.x;
    int t = threadIdx.x;

    // stage A[d] via cp.async (L2->smem, bypass L1; overlaps with gather below)
    const float4* Ab = (const float4*)(A + (size_t)d * DD * DD);
#pragma unroll
    for (int k = 0; k < 16; k++) {
        int r = k * 4 + (t >> 4), c = t & 15;
        uint32_t dst = (uint32_t)__cvta_generic_to_shared(&sA[r * 16 + (c ^ (r & 15))]);
        asm volatile("cp.async.cg.shared.global [%0], [%1], 16;"
                     :: "r"(dst), "l"(Ab + k * 64 + t));
    }
    asm volatile("cp.async.commit_group;");

    float au, ayv = 0.0f, av = 1.0f;
    if (first) {
        au = __ldg(xin + d * DD + t);
    } else {
        int beg = g_rs[d], end = g_rs[d + 1];
        au = mu[d * DD + t];
        ayv = my[d * DD + t];
        av = mv[d];
        for (int j = beg; j < end; j++) {
            int s = g_src[j];                 // broadcast load
            au  += __ldg(mu + s * DD + t);
            ayv += __ldg(my + s * DD + t);
            av  += __ldg(mv + s);             // broadcast load
        }
    }
    float inv = first ? 1.0f : (1.0f / av);
    float xval = au * inv;                    // x1 (or x for first)
    sx[t] = xval;

    asm volatile("cp.async.wait_group 0;");
    __syncthreads();

    const float4* sx4 = (const float4*)sx;
    float acc = 0.0f;
#pragma unroll
    for (int j = 0; j < 16; j++) {
        float4 a4 = sA[t * 16 + (j ^ (t & 15))];
        float4 x4 = sx4[j];
        acc += a4.x * x4.x + a4.y * x4.y + a4.z * x4.z + a4.w * x4.w;
    }

    int r = d * DD + t;
    float gv = 2.0f * acc + __ldg(b + r);
    float ynew = first ? gv : (ayv + gv - g[r]);
    g[r] = gv;
    float w = g_invd[d];
    muN[r] = (au * (first ? 1.0f : inv * av) - STEP * ynew) * w; // au is u_{L+1}
    myN[r] = ynew * w;
    if (t == 0) mvN[d] = av * w;
}

// Final layer: out = mix(u)/mix(v) only (y path dead)
__global__ void __launch_bounds__(64) k_final(const float* __restrict__ mu,
                                              const float* __restrict__ mv,
                                              float* __restrict__ out) {
    int d = blockIdx.x;
    int t = threadIdx.x;
    int beg = g_rs[d], end = g_rs[d + 1];
    float au = mu[d * DD + t];
    float av = mv[d];
    for (int j = beg; j < end; j++) {
        int s = g_src[j];
        au += __ldg(mu + s * DD + t);
        av += __ldg(mv + s);
    }
    out[d * DD + t] = au / av;
}

__global__ void k_tail(float* o, int start, int end, float val) {
    int i = start + blockIdx.x * blockDim.x + threadIdx.x;
    if (i < end) o[i] = val;
}

extern "C" void kernel_launch(void* const* d_in, const int* in_sizes, int n_in,
                              void* d_out, int out_size) {
    const float* A = (const float*)d_in[0];
    const float* b = (const float*)d_in[1];
    const float* x = (const float*)d_in[2];
    const int* ei = (const int*)d_in[3];   // int32 (JAX x64 disabled)
    float* out = (float*)d_out;

    float *muA, *muB, *myA, *myB, *mvA, *mvB, *g;
    cudaGetSymbolAddress((void**)&muA, g_muA);
    cudaGetSymbolAddress((void**)&muB, g_muB);
    cudaGetSymbolAddress((void**)&myA, g_myA);
    cudaGetSymbolAddress((void**)&myB, g_myB);
    cudaGetSymbolAddress((void**)&mvA, g_mvA);
    cudaGetSymbolAddress((void**)&mvB, g_mvB);
    cudaGetSymbolAddress((void**)&g,   g_g);

    // setup: degrees, weights, in-CSR
    k_cnt0<<<(NN + 255) / 256, 256>>>();
    k_count<<<(EE + 255) / 256, 256>>>(ei);
    k_invd<<<(NN + 255) / 256, 256>>>();
    k_scan<<<1, 1024>>>();
    k_sort<<<(EE + 255) / 256, 256>>>(ei);

    // layer 0 prologue: y0 = grad(x); emit messages into set A
    k_fused<<<NN, 64>>>(A, b, x, nullptr, nullptr, nullptr, g, muA, myA, mvA, 1);

    // 9 full layers (each consumes one set, emits the other)
    for (int L = 0; L < NL - 1; L++) {
        int p = L & 1;
        float* mu_i = p ? muB : muA;
        float* my_i = p ? myB : myA;
        float* mv_i = p ? mvB : mvA;
        float* mu_o = p ? muA : muB;
        float* my_o = p ? myA : myB;
        float* mv_o = p ? mvA : mvB;
        k_fused<<<NN, 64>>>(A, b, nullptr, mu_i, my_i, mv_i, g, mu_o, my_o, mv_o, 0);
    }

    // final layer: only u/v mix matter
    {
        int p = (NL - 1) & 1;
        float* mu_i = p ? muB : muA;
        float* mv_i = p ? mvB : mvA;
        k_final<<<NN, 64>>>(mu_i, mv_i, out);
    }

    if (out_size > ND) {
        float cc = (float)(3LL * NL * (long long)EE);
        int tail = out_size - ND;
        k_tail<<<(tail + 255) / 256, 256>>>(out, ND, out_size, cc);
    }
}